// round 14
// baseline (speedup 1.0000x reference)
#include <cuda_runtime.h>
#include <cuda_fp16.h>
#include <math.h>
#include <stdint.h>

#define TOK   2048
#define DDIM  1024
#define NEXP  15
#define KTOP  3
#define FF    1024
#define FSH   2048
#define NPAIR (TOK*KTOP)   // 6144

// ---------------- static scratch ----------------
__device__ __align__(16) float g_yp[(size_t)NPAIR * DDIM];        // expert fc2 out
__device__ __align__(16) __half g_xq [(size_t)TOK * DDIM];
__device__ __align__(16) __half g_aq [(size_t)NPAIR * FF];        // expert act (fp16)
__device__ __align__(16) __half g_asq[(size_t)TOK * FSH];         // shared act (fp16)
__device__ __align__(16) __half g_w1q[(size_t)NEXP * 2 * FF * DDIM];
__device__ __align__(16) __half g_w2q[(size_t)NEXP * DDIM * FF];
__device__ __align__(16) __half g_s1q[(size_t)2 * FSH * DDIM];
__device__ __align__(16) __half g_s2q[(size_t)DDIM * FSH];

__device__ int   g_ptok[NPAIR];
__device__ int   g_t2s [TOK * KTOP];
__device__ float g_tw  [TOK * KTOP];
__device__ int   g_ti  [TOK * KTOP];
__device__ int   g_cnt[NEXP], g_off[NEXP];

__device__ __forceinline__ float gelu_exact(float v) {
    return 0.5f * v * (1.0f + erff(v * 0.70710678118654752440f));
}
__device__ __forceinline__ uint32_t smem_u32(const void* p) {
    return (uint32_t)__cvta_generic_to_shared(p);
}
__device__ __forceinline__ uint32_t pack2h(float a, float b) {
    __half2 h = __floats2half2_rn(a, b);
    return *(uint32_t*)&h;
}

// ---------------- conversion kernel: grid-stride, 4-way MLP, coalesced ----------------
__global__ void k_cvt(const float4* __restrict__ src, uint2* __restrict__ dst, int n4) {
    int stride = gridDim.x * blockDim.x;
    int i0 = blockIdx.x * blockDim.x + threadIdx.x;
    for (int i = i0; i < n4; i += 4 * stride) {
#pragma unroll
        for (int j = 0; j < 4; j++) {
            int idx = i + j * stride;
            if (idx < n4) {
                float4 v = src[idx];
                uint2 o;
                o.x = pack2h(v.x, v.y);
                o.y = pack2h(v.z, v.w);
                dst[idx] = o;
            }
        }
    }
}

// ---------------- gating ----------------
__global__ void zero_kernel() {
    int i = threadIdx.x;
    if (i < NEXP) g_cnt[i] = 0;
}

__global__ void gate_kernel(const float* __restrict__ x, const float* __restrict__ gw) {
    int t = blockIdx.x;
    int tid = threadIdx.x;   // 128 threads
    float part[NEXP];
#pragma unroll
    for (int e = 0; e < NEXP; e++) part[e] = 0.f;
    const float* xr = x + (size_t)t * DDIM;
    for (int d = tid; d < DDIM; d += 128) {
        float xv = xr[d];
#pragma unroll
        for (int e = 0; e < NEXP; e++) part[e] += xv * gw[e * DDIM + d];
    }
#pragma unroll
    for (int e = 0; e < NEXP; e++)
#pragma unroll
        for (int o = 16; o > 0; o >>= 1)
            part[e] += __shfl_xor_sync(0xFFFFFFFFu, part[e], o);

    __shared__ float red[NEXP][4];
    int w = tid >> 5, l = tid & 31;
    if (l == 0)
#pragma unroll
        for (int e = 0; e < NEXP; e++) red[e][w] = part[e];
    __syncthreads();

    if (tid == 0) {
        float lg[NEXP];
#pragma unroll
        for (int e = 0; e < NEXP; e++)
            lg[e] = red[e][0] + red[e][1] + red[e][2] + red[e][3];
        float mx = lg[0];
#pragma unroll
        for (int e = 1; e < NEXP; e++) mx = fmaxf(mx, lg[e]);
        float s = 0.f, sc[NEXP];
#pragma unroll
        for (int e = 0; e < NEXP; e++) { sc[e] = expf(lg[e] - mx); s += sc[e]; }
        float inv = 1.f / s;
#pragma unroll
        for (int e = 0; e < NEXP; e++) sc[e] *= inv;

        int   idx[KTOP];
        float wv [KTOP];
        float wsum = 0.f;
#pragma unroll
        for (int k = 0; k < KTOP; k++) {
            int   bi = 0;
            float bv = -1.f;
#pragma unroll
            for (int e = 0; e < NEXP; e++)
                if (sc[e] > bv) { bv = sc[e]; bi = e; }
            idx[k] = bi; wv[k] = bv; wsum += bv;
            sc[bi] = -2.f;
        }
        float winv = 1.f / (wsum + 1e-20f);
#pragma unroll
        for (int k = 0; k < KTOP; k++) {
            g_ti[t * KTOP + k] = idx[k];
            g_tw[t * KTOP + k] = wv[k] * winv;
            atomicAdd(&g_cnt[idx[k]], 1);
        }
    }
}

__global__ void route_kernel() {
    __shared__ int cur[NEXP];
    int tid = threadIdx.x;           // 1024
    if (tid == 0) {
        int cum = 0;
        for (int e = 0; e < NEXP; e++) {
            g_off[e] = cum;
            cur[e] = cum;
            cum += g_cnt[e];
        }
    }
    __syncthreads();
#pragma unroll
    for (int rep = 0; rep < 2; rep++) {
        int t = tid + rep * 1024;
        if (t < TOK) {
#pragma unroll
            for (int k = 0; k < KTOP; k++) {
                int e = g_ti[t * KTOP + k];
                int s = atomicAdd(&cur[e], 1);
                g_ptok[s] = t;
                g_t2s[t * KTOP + k] = s;
            }
        }
    }
}

// ---------------- fp16 mma.sync GEMM, 3-stage cp.async ----------------
// MTILE=64: CTA 64x128, 8 warps of 32x32 (NI=2). MTILE=32: CTA 32x128, 8 warps of 16x32 (NI=1).
#define BK  32
#define TS  80
#define NSTAGE 3
#define TILE_BB (128*TS)               // 10240
#define SMEM_G(MT) (NSTAGE*((MT)*TS + TILE_BB))

extern __shared__ char smem_dyn[];

__device__ __forceinline__ void cp16(uint32_t dst, const void* src) {
    asm volatile("cp.async.cg.shared.global [%0], [%1], 16;" :: "r"(dst), "l"(src));
}
__device__ __forceinline__ void cp_commit() { asm volatile("cp.async.commit_group;"); }
__device__ __forceinline__ void cp_wait1() { asm volatile("cp.async.wait_group 1;"); }

__device__ __forceinline__ void ldsm4(uint32_t* r, uint32_t addr) {
    asm volatile("ldmatrix.sync.aligned.m8n8.x4.shared.b16 {%0,%1,%2,%3}, [%4];"
                 : "=r"(r[0]), "=r"(r[1]), "=r"(r[2]), "=r"(r[3]) : "r"(addr));
}
__device__ __forceinline__ void mma16816(float* d, const uint32_t* a, const uint32_t* b) {
    asm volatile("mma.sync.aligned.m16n8k16.row.col.f32.f16.f16.f32 "
                 "{%0,%1,%2,%3},{%4,%5,%6,%7},{%8,%9},{%0,%1,%2,%3};"
                 : "+f"(d[0]), "+f"(d[1]), "+f"(d[2]), "+f"(d[3])
                 : "r"(a[0]), "r"(a[1]), "r"(a[2]), "r"(a[3]), "r"(b[0]), "r"(b[1]));
}

template <int MTILE, bool GATHER, bool GEGLU>
__device__ void mm_gemm(const __half* __restrict__ A, int lda,
                        const int* __restrict__ ridx, int M,
                        const __half* __restrict__ B, int ldb,
                        const float* __restrict__ bias,
                        float* __restrict__ C, __half* __restrict__ Cq,
                        int ldc, int K, int H, const float* __restrict__ mult)
{
    constexpr int TILE_A = MTILE * TS;
    constexpr int STG_B = TILE_A + TILE_BB;
    constexpr int WROWS = MTILE / 2;      // rows per warp-m half
    constexpr int NI = WROWS / 16;        // m16 blocks per warp

    int m0 = blockIdx.x * MTILE;
    if (m0 >= M) return;

    int tid = threadIdx.x;             // 256
    int wid = tid >> 5, lane = tid & 31;
    uint32_t sBase = smem_u32(smem_dyn);

    // ---- A loader: 4 chunks of 16B per row; MTILE*4 slots ----
    int lrowA = tid >> 2, chA = tid & 3;
    bool aActive = (MTILE == 64) || (tid < 128);
    int gm = m0 + (aActive ? lrowA : 0);
    int ga = 0;
    if (aActive && gm < M) ga = GATHER ? ridx[gm] : gm;
    const __half* pa = A + (size_t)ga * lda + chA * 8;
    uint32_t dstA = (uint32_t)(lrowA * TS + chA * 16);

    // ---- B loader: 2 threads per row, two 16B chunks each ----
    int lrowB = tid >> 1, chB = (tid & 1) * 2;
    int grow;
    if (GEGLU) {
        int b = lrowB >> 3, o = lrowB & 7;
        int f = blockIdx.y * 64 + (b >> 1) * 8 + o;
        grow = (b & 1) ? (H + f) : f;
    } else {
        grow = blockIdx.y * 128 + lrowB;
    }
    const __half* pb = B + (size_t)grow * ldb + chB * 8;
    uint32_t dstB = (uint32_t)(lrowB * TS + chB * 16);

    // ---- warp tile: 2x4 warps ----
    int wm = wid >> 2;
    int wn = wid & 3;
    uint32_t aoff = (uint32_t)((wm * WROWS + (lane & 15)) * TS) + ((lane >> 4) << 4);
    uint32_t boff = (uint32_t)((wn * 32 + (lane & 7) + ((lane >> 4) & 1) * 8) * TS)
                  + (((lane >> 3) & 1) << 4);

    float acc[NI][4][4];
#pragma unroll
    for (int i = 0; i < NI; i++)
#pragma unroll
        for (int j = 0; j < 4; j++)
#pragma unroll
            for (int c = 0; c < 4; c++) acc[i][j][c] = 0.f;

    int NT = K / BK;

    auto issue = [&](int it) {
        uint32_t sb = sBase + (uint32_t)(it % NSTAGE) * STG_B;
        int k0 = it * BK;
        if (aActive) cp16(sb + dstA, pa + k0);
        cp16(sb + TILE_A + dstB,      pb + k0);
        cp16(sb + TILE_A + dstB + 16, pb + k0 + 8);
    };

    issue(0); cp_commit();
    issue(1); cp_commit();

    for (int it = 0; it < NT; it++) {
        cp_wait1();
        __syncthreads();
        if (it + 2 < NT) { issue(it + 2); }
        cp_commit();

        uint32_t stg = sBase + (uint32_t)(it % NSTAGE) * STG_B;
        uint32_t As = stg + aoff;
        uint32_t Bs = stg + TILE_A + boff;
#pragma unroll
        for (int k16 = 0; k16 < 2; k16++) {
            uint32_t a[NI][4], b[2][4];
#pragma unroll
            for (int jj = 0; jj < 2; jj++) ldsm4(b[jj], Bs + jj * 16 * TS + k16 * 32);
#pragma unroll
            for (int i = 0; i < NI; i++) {
                ldsm4(a[i], As + i * 16 * TS + k16 * 32);
#pragma unroll
                for (int j = 0; j < 4; j++)
                    mma16816(acc[i][j], a[i], &b[j >> 1][(j & 1) * 2]);
            }
        }
    }

    int rbase = m0 + wm * WROWS + (lane >> 2);

    if (GEGLU) {
#pragma unroll
        for (int jp = 0; jp < 2; jp++) {
            int f = blockIdx.y * 64 + (wn * 2 + jp) * 8 + (lane & 3) * 2;
            float bx0 = bias[f],     bx1 = bias[f + 1];
            float bg0 = bias[H + f], bg1 = bias[H + f + 1];
            float mu0 = mult[f],     mu1 = mult[f + 1];
#pragma unroll
            for (int i = 0; i < NI; i++) {
                int r = rbase + i * 16;
                float* xh = acc[i][2 * jp];
                float* gg = acc[i][2 * jp + 1];
                if (r < M) {
                    float a0 = gelu_exact(gg[0] + bg0) * (xh[0] + bx0) * mu0;
                    float a1 = gelu_exact(gg[1] + bg1) * (xh[1] + bx1) * mu1;
                    *(uint32_t*)(Cq + (size_t)r * H + f) = pack2h(a0, a1);
                }
                if (r + 8 < M) {
                    float a0 = gelu_exact(gg[2] + bg0) * (xh[2] + bx0) * mu0;
                    float a1 = gelu_exact(gg[3] + bg1) * (xh[3] + bx1) * mu1;
                    *(uint32_t*)(Cq + (size_t)(r + 8) * H + f) = pack2h(a0, a1);
                }
            }
        }
    } else {
        int cbase = blockIdx.y * 128 + wn * 32 + (lane & 3) * 2;
#pragma unroll
        for (int i = 0; i < NI; i++) {
#pragma unroll
            for (int j = 0; j < 4; j++) {
                int r = rbase + i * 16;
                int c = cbase + j * 8;
                float b0 = bias[c], b1 = bias[c + 1];
                if (r < M) {
                    float2 o = make_float2(acc[i][j][0] + b0, acc[i][j][1] + b1);
                    *(float2*)(C + (size_t)r * ldc + c) = o;
                }
                if (r + 8 < M) {
                    float2 o = make_float2(acc[i][j][2] + b0, acc[i][j][3] + b1);
                    *(float2*)(C + (size_t)(r + 8) * ldc + c) = o;
                }
            }
        }
    }
}

// ---------------- GEMM wrappers ----------------
__global__ void __launch_bounds__(256, 4) k_efc1(const float* __restrict__ b,
                                                 const float* __restrict__ mult) {
    int e = blockIdx.z;
    int M = g_cnt[e], off = g_off[e];
    mm_gemm<32, true, true>(g_xq, DDIM, g_ptok + off, M,
                            g_w1q + (size_t)e * 2 * FF * DDIM, DDIM,
                            b + (size_t)e * 2 * FF,
                            nullptr, g_aq + (size_t)off * FF,
                            0, DDIM, FF, mult + (size_t)e * FF);
}

__global__ void __launch_bounds__(256, 4) k_efc2(const float* __restrict__ b) {
    int e = blockIdx.z;
    int M = g_cnt[e], off = g_off[e];
    mm_gemm<32, false, false>(g_aq + (size_t)off * FF, FF, nullptr, M,
                              g_w2q + (size_t)e * DDIM * FF, FF,
                              b + (size_t)e * DDIM,
                              g_yp + (size_t)off * DDIM, nullptr,
                              DDIM, FF, 0, nullptr);
}

__global__ void __launch_bounds__(256, 3) k_sfc1(const float* __restrict__ b,
                                                 const float* __restrict__ mult) {
    mm_gemm<64, false, true>(g_xq, DDIM, nullptr, TOK, g_s1q, DDIM, b,
                             nullptr, g_asq, 0, DDIM, FSH, mult);
}

__global__ void __launch_bounds__(256, 3) k_sfc2(const float* __restrict__ b,
                                                 float* __restrict__ out) {
    mm_gemm<64, false, false>(g_asq, FSH, nullptr, TOK, g_s2q, FSH, b,
                              out, nullptr, DDIM, FSH, 0, nullptr);
}

// ---------------- combine ----------------
__global__ void k_comb(float* __restrict__ out) {
    int i = blockIdx.x * blockDim.x + threadIdx.x;
    const int D4 = DDIM / 4;
    if (i >= TOK * D4) return;
    int t = i / D4, d4 = i % D4;
    float4 acc = *(float4*)(out + (size_t)t * DDIM + d4 * 4);
#pragma unroll
    for (int k = 0; k < KTOP; k++) {
        int s = g_t2s[t * KTOP + k];
        float w = g_tw[t * KTOP + k];
        const float4 v = *(const float4*)(g_yp + (size_t)s * DDIM + d4 * 4);
        acc.x += w * v.x; acc.y += w * v.y; acc.z += w * v.z; acc.w += w * v.w;
    }
    *(float4*)(out + (size_t)t * DDIM + d4 * 4) = acc;
}

// ---------------- launch ----------------
#define CVT_SMALL_GRID 296

extern "C" void kernel_launch(void* const* d_in, const int* in_sizes, int n_in,
                              void* d_out, int out_size) {
    const float* x       = (const float*)d_in[0];
    const float* gate_w  = (const float*)d_in[1];
    const float* fc1_w   = (const float*)d_in[2];
    const float* fc1_b   = (const float*)d_in[3];
    const float* gmult   = (const float*)d_in[4];
    const float* fc2_w   = (const float*)d_in[5];
    const float* fc2_b   = (const float*)d_in[6];
    const float* sfc1_w  = (const float*)d_in[7];
    const float* sfc1_b  = (const float*)d_in[8];
    const float* sgmult  = (const float*)d_in[9];
    const float* sfc2_w  = (const float*)d_in[10];
    const float* sfc2_b  = (const float*)d_in[11];
    float* out = (float*)d_out;

    static bool inited = false;
    static cudaStream_t sB, sC;
    static cudaEvent_t evF, evX, evB1, evB2, evC;
    if (!inited) {
        cudaStreamCreateWithFlags(&sB, cudaStreamNonBlocking);
        cudaStreamCreateWithFlags(&sC, cudaStreamNonBlocking);
        cudaEventCreateWithFlags(&evF,  cudaEventDisableTiming);
        cudaEventCreateWithFlags(&evX,  cudaEventDisableTiming);
        cudaEventCreateWithFlags(&evB1, cudaEventDisableTiming);
        cudaEventCreateWithFlags(&evB2, cudaEventDisableTiming);
        cudaEventCreateWithFlags(&evC,  cudaEventDisableTiming);
        cudaFuncSetAttribute(k_efc1, cudaFuncAttributeMaxDynamicSharedMemorySize, SMEM_G(32));
        cudaFuncSetAttribute(k_efc2, cudaFuncAttributeMaxDynamicSharedMemorySize, SMEM_G(32));
        cudaFuncSetAttribute(k_sfc1, cudaFuncAttributeMaxDynamicSharedMemorySize, SMEM_G(64));
        cudaFuncSetAttribute(k_sfc2, cudaFuncAttributeMaxDynamicSharedMemorySize, SMEM_G(64));
        inited = true;
    }

    __half *xq, *w1q, *w2q, *s1q, *s2q;
    cudaGetSymbolAddress((void**)&xq,  g_xq);
    cudaGetSymbolAddress((void**)&w1q, g_w1q);
    cudaGetSymbolAddress((void**)&w2q, g_w2q);
    cudaGetSymbolAddress((void**)&s1q, g_s1q);
    cudaGetSymbolAddress((void**)&s2q, g_s2q);

    // fork
    cudaEventRecord(evF, 0);
    cudaStreamWaitEvent(sB, evF, 0);
    cudaStreamWaitEvent(sC, evF, 0);

    // ---- stream L: gating + routing (reads fp32 x) ----
    zero_kernel<<<1, 32>>>();
    gate_kernel<<<TOK, 128>>>(x, gate_w);
    route_kernel<<<1, 1024>>>();

    // ---- stream B: w1 conversion (head-critical, big grid), then w2 (throttled) ----
    {
        int n4 = NEXP * 2 * FF * DDIM / 4;
        k_cvt<<<2048, 256, 0, sB>>>((const float4*)fc1_w, (uint2*)w1q, n4);
        cudaEventRecord(evB1, sB);
        n4 = NEXP * DDIM * FF / 4;
        k_cvt<<<CVT_SMALL_GRID, 256, 0, sB>>>((const float4*)fc2_w, (uint2*)w2q, n4);
        cudaEventRecord(evB2, sB);
    }

    // ---- stream C: xcvt -> s1cvt -> sfc1 -> s2cvt -> sfc2 ----
    {
        int n4 = TOK * DDIM / 4;
        k_cvt<<<CVT_SMALL_GRID, 256, 0, sC>>>((const float4*)x, (uint2*)xq, n4);
        cudaEventRecord(evX, sC);
        n4 = 2 * FSH * DDIM / 4;
        k_cvt<<<CVT_SMALL_GRID, 256, 0, sC>>>((const float4*)sfc1_w, (uint2*)s1q, n4);
        dim3 g3(TOK / 64, FSH / 64);
        k_sfc1<<<g3, 256, SMEM_G(64), sC>>>(sfc1_b, sgmult);
        n4 = DDIM * FSH / 4;
        k_cvt<<<CVT_SMALL_GRID, 256, 0, sC>>>((const float4*)sfc2_w, (uint2*)s2q, n4);
        dim3 g4(TOK / 64, DDIM / 128);
        k_sfc2<<<g4, 256, SMEM_G(64), sC>>>(sfc2_b, out);
        cudaEventRecord(evC, sC);
    }

    // ---- stream L: expert chain (32-row M tiles) ----
    cudaStreamWaitEvent(0, evX, 0);
    cudaStreamWaitEvent(0, evB1, 0);
    dim3 g1(NPAIR / 32, FF / 64, NEXP);
    k_efc1<<<g1, 256, SMEM_G(32)>>>(fc1_b, gmult);
    cudaStreamWaitEvent(0, evB2, 0);
    dim3 g2(NPAIR / 32, DDIM / 128, NEXP);
    k_efc2<<<g2, 256, SMEM_G(32)>>>(fc2_b);

    // join + combine
    cudaStreamWaitEvent(0, evC, 0);
    k_comb<<<(TOK * (DDIM / 4) + 255) / 256, 256>>>(out);
}

// round 15
// speedup vs baseline: 1.1891x; 1.1891x over previous
#include <cuda_runtime.h>
#include <cuda_fp16.h>
#include <math.h>
#include <stdint.h>

#define TOK   2048
#define DDIM  1024
#define NEXP  15
#define KTOP  3
#define FF    1024
#define FSH   2048
#define NPAIR (TOK*KTOP)   // 6144

// ---------------- static scratch ----------------
__device__ __align__(16) float g_yp[(size_t)NPAIR * DDIM];        // expert fc2 out
__device__ __align__(16) __half g_xq [(size_t)TOK * DDIM];
__device__ __align__(16) __half g_aq [(size_t)NPAIR * FF];        // expert act (fp16)
__device__ __align__(16) __half g_asq[(size_t)TOK * FSH];         // shared act (fp16)
__device__ __align__(16) __half g_w1q[(size_t)NEXP * 2 * FF * DDIM];
__device__ __align__(16) __half g_w2q[(size_t)NEXP * DDIM * FF];
__device__ __align__(16) __half g_s1q[(size_t)2 * FSH * DDIM];
__device__ __align__(16) __half g_s2q[(size_t)DDIM * FSH];

__device__ int   g_ptok[NPAIR];
__device__ int   g_t2s [TOK * KTOP];
__device__ float g_tw  [TOK * KTOP];
__device__ int   g_ti  [TOK * KTOP];
__device__ int   g_cnt[NEXP], g_off[NEXP];

__device__ __forceinline__ float gelu_exact(float v) {
    return 0.5f * v * (1.0f + erff(v * 0.70710678118654752440f));
}
__device__ __forceinline__ uint32_t smem_u32(const void* p) {
    return (uint32_t)__cvta_generic_to_shared(p);
}
__device__ __forceinline__ uint32_t pack2h(float a, float b) {
    __half2 h = __floats2half2_rn(a, b);
    return *(uint32_t*)&h;
}

// ---------------- conversion kernel: grid-stride, 4-way MLP, coalesced ----------------
__global__ void k_cvt(const float4* __restrict__ src, uint2* __restrict__ dst, int n4) {
    int stride = gridDim.x * blockDim.x;
    int i0 = blockIdx.x * blockDim.x + threadIdx.x;
    for (int i = i0; i < n4; i += 4 * stride) {
#pragma unroll
        for (int j = 0; j < 4; j++) {
            int idx = i + j * stride;
            if (idx < n4) {
                float4 v = src[idx];
                uint2 o;
                o.x = pack2h(v.x, v.y);
                o.y = pack2h(v.z, v.w);
                dst[idx] = o;
            }
        }
    }
}

// ---------------- gating ----------------
__global__ void zero_kernel() {
    int i = threadIdx.x;
    if (i < NEXP) g_cnt[i] = 0;
}

__global__ void gate_kernel(const float* __restrict__ x, const float* __restrict__ gw) {
    int t = blockIdx.x;
    int tid = threadIdx.x;   // 128 threads
    float part[NEXP];
#pragma unroll
    for (int e = 0; e < NEXP; e++) part[e] = 0.f;
    const float* xr = x + (size_t)t * DDIM;
    for (int d = tid; d < DDIM; d += 128) {
        float xv = xr[d];
#pragma unroll
        for (int e = 0; e < NEXP; e++) part[e] += xv * gw[e * DDIM + d];
    }
#pragma unroll
    for (int e = 0; e < NEXP; e++)
#pragma unroll
        for (int o = 16; o > 0; o >>= 1)
            part[e] += __shfl_xor_sync(0xFFFFFFFFu, part[e], o);

    __shared__ float red[NEXP][4];
    int w = tid >> 5, l = tid & 31;
    if (l == 0)
#pragma unroll
        for (int e = 0; e < NEXP; e++) red[e][w] = part[e];
    __syncthreads();

    if (tid == 0) {
        float lg[NEXP];
#pragma unroll
        for (int e = 0; e < NEXP; e++)
            lg[e] = red[e][0] + red[e][1] + red[e][2] + red[e][3];
        float mx = lg[0];
#pragma unroll
        for (int e = 1; e < NEXP; e++) mx = fmaxf(mx, lg[e]);
        float s = 0.f, sc[NEXP];
#pragma unroll
        for (int e = 0; e < NEXP; e++) { sc[e] = expf(lg[e] - mx); s += sc[e]; }
        float inv = 1.f / s;
#pragma unroll
        for (int e = 0; e < NEXP; e++) sc[e] *= inv;

        int   idx[KTOP];
        float wv [KTOP];
        float wsum = 0.f;
#pragma unroll
        for (int k = 0; k < KTOP; k++) {
            int   bi = 0;
            float bv = -1.f;
#pragma unroll
            for (int e = 0; e < NEXP; e++)
                if (sc[e] > bv) { bv = sc[e]; bi = e; }
            idx[k] = bi; wv[k] = bv; wsum += bv;
            sc[bi] = -2.f;
        }
        float winv = 1.f / (wsum + 1e-20f);
#pragma unroll
        for (int k = 0; k < KTOP; k++) {
            g_ti[t * KTOP + k] = idx[k];
            g_tw[t * KTOP + k] = wv[k] * winv;
            atomicAdd(&g_cnt[idx[k]], 1);
        }
    }
}

__global__ void route_kernel() {
    __shared__ int cur[NEXP];
    int tid = threadIdx.x;           // 1024
    if (tid == 0) {
        int cum = 0;
        for (int e = 0; e < NEXP; e++) {
            g_off[e] = cum;
            cur[e] = cum;
            cum += g_cnt[e];
        }
    }
    __syncthreads();
#pragma unroll
    for (int rep = 0; rep < 2; rep++) {
        int t = tid + rep * 1024;
        if (t < TOK) {
#pragma unroll
            for (int k = 0; k < KTOP; k++) {
                int e = g_ti[t * KTOP + k];
                int s = atomicAdd(&cur[e], 1);
                g_ptok[s] = t;
                g_t2s[t * KTOP + k] = s;
            }
        }
    }
}

// ---------------- fp16 mma.sync GEMM: CTA 64x128, 8 warps of 32x32, 4-stage cp.async ----------------
#define BK  32
#define TS  80
#define NSTAGE 4
#define TILE_A (64*TS)                 // 5120
#define TILE_BB (128*TS)               // 10240
#define STG_B (TILE_A + TILE_BB)       // 15360
#define SMEM_GEMM (NSTAGE*STG_B)       // 61440

extern __shared__ char smem_dyn[];

__device__ __forceinline__ void cp16(uint32_t dst, const void* src) {
    asm volatile("cp.async.cg.shared.global [%0], [%1], 16;" :: "r"(dst), "l"(src));
}
__device__ __forceinline__ void cp_commit() { asm volatile("cp.async.commit_group;"); }
__device__ __forceinline__ void cp_wait2() { asm volatile("cp.async.wait_group 2;"); }

__device__ __forceinline__ void ldsm4(uint32_t* r, uint32_t addr) {
    asm volatile("ldmatrix.sync.aligned.m8n8.x4.shared.b16 {%0,%1,%2,%3}, [%4];"
                 : "=r"(r[0]), "=r"(r[1]), "=r"(r[2]), "=r"(r[3]) : "r"(addr));
}
__device__ __forceinline__ void mma16816(float* d, const uint32_t* a, const uint32_t* b) {
    asm volatile("mma.sync.aligned.m16n8k16.row.col.f32.f16.f16.f32 "
                 "{%0,%1,%2,%3},{%4,%5,%6,%7},{%8,%9},{%0,%1,%2,%3};"
                 : "+f"(d[0]), "+f"(d[1]), "+f"(d[2]), "+f"(d[3])
                 : "r"(a[0]), "r"(a[1]), "r"(a[2]), "r"(a[3]), "r"(b[0]), "r"(b[1]));
}

template <bool GATHER, bool GEGLU>
__device__ void mm_gemm(const __half* __restrict__ A, int lda,
                        const int* __restrict__ ridx, int M,
                        const __half* __restrict__ B, int ldb,
                        const float* __restrict__ bias,
                        float* __restrict__ C, __half* __restrict__ Cq,
                        int ldc, int K, int H, const float* __restrict__ mult)
{
    int m0 = blockIdx.x * 64;
    if (m0 >= M) return;

    int tid = threadIdx.x;             // 256
    int wid = tid >> 5, lane = tid & 31;
    uint32_t sBase = smem_u32(smem_dyn);

    // ---- A loader: 4 threads per row, one 16B chunk each ----
    int lrowA = tid >> 2, chA = tid & 3;
    int gm = m0 + lrowA;
    int ga = 0;
    if (gm < M) ga = GATHER ? ridx[gm] : gm;
    const __half* pa = A + (size_t)ga * lda + chA * 8;
    uint32_t dstA = (uint32_t)(lrowA * TS + chA * 16);

    // ---- B loader: 2 threads per row, two 16B chunks each ----
    int lrowB = tid >> 1, chB = (tid & 1) * 2;
    int grow;
    if (GEGLU) {
        int b = lrowB >> 3, o = lrowB & 7;
        int f = blockIdx.y * 64 + (b >> 1) * 8 + o;
        grow = (b & 1) ? (H + f) : f;
    } else {
        grow = blockIdx.y * 128 + lrowB;
    }
    const __half* pb = B + (size_t)grow * ldb + chB * 8;
    uint32_t dstB = (uint32_t)(lrowB * TS + chB * 16);

    // ---- warp tile: 2x4 warps of 32x32 ----
    int wm = wid >> 2;
    int wn = wid & 3;
    uint32_t aoff = (uint32_t)((wm * 32 + (lane & 15)) * TS) + ((lane >> 4) << 4);
    uint32_t boff = (uint32_t)((wn * 32 + (lane & 7) + ((lane >> 4) & 1) * 8) * TS)
                  + (((lane >> 3) & 1) << 4);

    float acc[2][4][4];
#pragma unroll
    for (int i = 0; i < 2; i++)
#pragma unroll
        for (int j = 0; j < 4; j++)
#pragma unroll
            for (int c = 0; c < 4; c++) acc[i][j][c] = 0.f;

    int NT = K / BK;

    auto issue = [&](int it) {
        uint32_t sb = sBase + (uint32_t)(it % NSTAGE) * STG_B;
        int k0 = it * BK;
        cp16(sb + dstA, pa + k0);
        cp16(sb + TILE_A + dstB,      pb + k0);
        cp16(sb + TILE_A + dstB + 16, pb + k0 + 8);
    };

    issue(0); cp_commit();
    issue(1); cp_commit();
    issue(2); cp_commit();

    for (int it = 0; it < NT; it++) {
        cp_wait2();
        __syncthreads();
        if (it + 3 < NT) { issue(it + 3); }
        cp_commit();

        uint32_t stg = sBase + (uint32_t)(it % NSTAGE) * STG_B;
        uint32_t As = stg + aoff;
        uint32_t Bs = stg + TILE_A + boff;
#pragma unroll
        for (int k16 = 0; k16 < 2; k16++) {
            uint32_t a[2][4], b[2][4];
#pragma unroll
            for (int jj = 0; jj < 2; jj++) ldsm4(b[jj], Bs + jj * 16 * TS + k16 * 32);
#pragma unroll
            for (int i = 0; i < 2; i++) {
                ldsm4(a[i], As + i * 16 * TS + k16 * 32);
#pragma unroll
                for (int j = 0; j < 4; j++)
                    mma16816(acc[i][j], a[i], &b[j >> 1][(j & 1) * 2]);
            }
        }
    }

    int rbase = m0 + wm * 32 + (lane >> 2);

    if (GEGLU) {
#pragma unroll
        for (int jp = 0; jp < 2; jp++) {
            int f = blockIdx.y * 64 + (wn * 2 + jp) * 8 + (lane & 3) * 2;
            float bx0 = bias[f],     bx1 = bias[f + 1];
            float bg0 = bias[H + f], bg1 = bias[H + f + 1];
            float mu0 = mult[f],     mu1 = mult[f + 1];
#pragma unroll
            for (int i = 0; i < 2; i++) {
                int r = rbase + i * 16;
                float* xh = acc[i][2 * jp];
                float* gg = acc[i][2 * jp + 1];
                if (r < M) {
                    float a0 = gelu_exact(gg[0] + bg0) * (xh[0] + bx0) * mu0;
                    float a1 = gelu_exact(gg[1] + bg1) * (xh[1] + bx1) * mu1;
                    *(uint32_t*)(Cq + (size_t)r * H + f) = pack2h(a0, a1);
                }
                if (r + 8 < M) {
                    float a0 = gelu_exact(gg[2] + bg0) * (xh[2] + bx0) * mu0;
                    float a1 = gelu_exact(gg[3] + bg1) * (xh[3] + bx1) * mu1;
                    *(uint32_t*)(Cq + (size_t)(r + 8) * H + f) = pack2h(a0, a1);
                }
            }
        }
    } else {
        int cbase = blockIdx.y * 128 + wn * 32 + (lane & 3) * 2;
#pragma unroll
        for (int i = 0; i < 2; i++) {
#pragma unroll
            for (int j = 0; j < 4; j++) {
                int r = rbase + i * 16;
                int c = cbase + j * 8;
                float b0 = bias[c], b1 = bias[c + 1];
                if (r < M) {
                    float2 o = make_float2(acc[i][j][0] + b0, acc[i][j][1] + b1);
                    *(float2*)(C + (size_t)r * ldc + c) = o;
                }
                if (r + 8 < M) {
                    float2 o = make_float2(acc[i][j][2] + b0, acc[i][j][3] + b1);
                    *(float2*)(C + (size_t)(r + 8) * ldc + c) = o;
                }
            }
        }
    }
}

// ---------------- GEMM wrappers ----------------
__global__ void __launch_bounds__(256, 3) k_efc1(const float* __restrict__ b,
                                                 const float* __restrict__ mult) {
    int e = blockIdx.z;
    int M = g_cnt[e], off = g_off[e];
    mm_gemm<true, true>(g_xq, DDIM, g_ptok + off, M,
                        g_w1q + (size_t)e * 2 * FF * DDIM, DDIM,
                        b + (size_t)e * 2 * FF,
                        nullptr, g_aq + (size_t)off * FF,
                        0, DDIM, FF, mult + (size_t)e * FF);
}

__global__ void __launch_bounds__(256, 3) k_efc2(const float* __restrict__ b) {
    int e = blockIdx.z;
    int M = g_cnt[e], off = g_off[e];
    mm_gemm<false, false>(g_aq + (size_t)off * FF, FF, nullptr, M,
                          g_w2q + (size_t)e * DDIM * FF, FF,
                          b + (size_t)e * DDIM,
                          g_yp + (size_t)off * DDIM, nullptr,
                          DDIM, FF, 0, nullptr);
}

__global__ void __launch_bounds__(256, 3) k_sfc1(const float* __restrict__ b,
                                                 const float* __restrict__ mult) {
    mm_gemm<false, true>(g_xq, DDIM, nullptr, TOK, g_s1q, DDIM, b,
                         nullptr, g_asq, 0, DDIM, FSH, mult);
}

__global__ void __launch_bounds__(256, 3) k_sfc2(const float* __restrict__ b,
                                                 float* __restrict__ out) {
    mm_gemm<false, false>(g_asq, FSH, nullptr, TOK, g_s2q, FSH, b,
                          out, nullptr, DDIM, FSH, 0, nullptr);
}

// ---------------- combine ----------------
__global__ void k_comb(float* __restrict__ out) {
    int i = blockIdx.x * blockDim.x + threadIdx.x;
    const int D4 = DDIM / 4;
    if (i >= TOK * D4) return;
    int t = i / D4, d4 = i % D4;
    float4 acc = *(float4*)(out + (size_t)t * DDIM + d4 * 4);
#pragma unroll
    for (int k = 0; k < KTOP; k++) {
        int s = g_t2s[t * KTOP + k];
        float w = g_tw[t * KTOP + k];
        const float4 v = *(const float4*)(g_yp + (size_t)s * DDIM + d4 * 4);
        acc.x += w * v.x; acc.y += w * v.y; acc.z += w * v.z; acc.w += w * v.w;
    }
    *(float4*)(out + (size_t)t * DDIM + d4 * 4) = acc;
}

// ---------------- launch ----------------
#define CVT_SMALL_GRID 296

extern "C" void kernel_launch(void* const* d_in, const int* in_sizes, int n_in,
                              void* d_out, int out_size) {
    const float* x       = (const float*)d_in[0];
    const float* gate_w  = (const float*)d_in[1];
    const float* fc1_w   = (const float*)d_in[2];
    const float* fc1_b   = (const float*)d_in[3];
    const float* gmult   = (const float*)d_in[4];
    const float* fc2_w   = (const float*)d_in[5];
    const float* fc2_b   = (const float*)d_in[6];
    const float* sfc1_w  = (const float*)d_in[7];
    const float* sfc1_b  = (const float*)d_in[8];
    const float* sgmult  = (const float*)d_in[9];
    const float* sfc2_w  = (const float*)d_in[10];
    const float* sfc2_b  = (const float*)d_in[11];
    float* out = (float*)d_out;

    static bool inited = false;
    static cudaStream_t sB, sC;
    static cudaEvent_t evF, evX, evB1, evB2, evC;
    if (!inited) {
        cudaStreamCreateWithFlags(&sB, cudaStreamNonBlocking);
        cudaStreamCreateWithFlags(&sC, cudaStreamNonBlocking);
        cudaEventCreateWithFlags(&evF,  cudaEventDisableTiming);
        cudaEventCreateWithFlags(&evX,  cudaEventDisableTiming);
        cudaEventCreateWithFlags(&evB1, cudaEventDisableTiming);
        cudaEventCreateWithFlags(&evB2, cudaEventDisableTiming);
        cudaEventCreateWithFlags(&evC,  cudaEventDisableTiming);
        cudaFuncSetAttribute(k_efc1, cudaFuncAttributeMaxDynamicSharedMemorySize, SMEM_GEMM);
        cudaFuncSetAttribute(k_efc2, cudaFuncAttributeMaxDynamicSharedMemorySize, SMEM_GEMM);
        cudaFuncSetAttribute(k_sfc1, cudaFuncAttributeMaxDynamicSharedMemorySize, SMEM_GEMM);
        cudaFuncSetAttribute(k_sfc2, cudaFuncAttributeMaxDynamicSharedMemorySize, SMEM_GEMM);
        inited = true;
    }

    __half *xq, *w1q, *w2q, *s1q, *s2q;
    cudaGetSymbolAddress((void**)&xq,  g_xq);
    cudaGetSymbolAddress((void**)&w1q, g_w1q);
    cudaGetSymbolAddress((void**)&w2q, g_w2q);
    cudaGetSymbolAddress((void**)&s1q, g_s1q);
    cudaGetSymbolAddress((void**)&s2q, g_s2q);

    // fork
    cudaEventRecord(evF, 0);
    cudaStreamWaitEvent(sB, evF, 0);
    cudaStreamWaitEvent(sC, evF, 0);

    // ---- stream L: gating + routing (reads fp32 x) ----
    zero_kernel<<<1, 32>>>();
    gate_kernel<<<TOK, 128>>>(x, gate_w);
    route_kernel<<<1, 1024>>>();

    // ---- stream B: w1 conversion (head-critical, big grid), then w2 (throttled) ----
    {
        int n4 = NEXP * 2 * FF * DDIM / 4;
        k_cvt<<<2048, 256, 0, sB>>>((const float4*)fc1_w, (uint2*)w1q, n4);
        cudaEventRecord(evB1, sB);
        n4 = NEXP * DDIM * FF / 4;
        k_cvt<<<CVT_SMALL_GRID, 256, 0, sB>>>((const float4*)fc2_w, (uint2*)w2q, n4);
        cudaEventRecord(evB2, sB);
    }

    // ---- stream C: xcvt -> s1cvt -> sfc1 -> s2cvt -> sfc2 ----
    {
        int n4 = TOK * DDIM / 4;
        k_cvt<<<CVT_SMALL_GRID, 256, 0, sC>>>((const float4*)x, (uint2*)xq, n4);
        cudaEventRecord(evX, sC);
        n4 = 2 * FSH * DDIM / 4;
        k_cvt<<<CVT_SMALL_GRID, 256, 0, sC>>>((const float4*)sfc1_w, (uint2*)s1q, n4);
        dim3 g3(TOK / 64, FSH / 64);
        k_sfc1<<<g3, 256, SMEM_GEMM, sC>>>(sfc1_b, sgmult);
        int n4b = DDIM * FSH / 4;
        k_cvt<<<CVT_SMALL_GRID, 256, 0, sC>>>((const float4*)sfc2_w, (uint2*)s2q, n4b);
        dim3 g4(TOK / 64, DDIM / 128);
        k_sfc2<<<g4, 256, SMEM_GEMM, sC>>>(sfc2_b, out);
        cudaEventRecord(evC, sC);
    }

    // ---- stream L: expert chain ----
    cudaStreamWaitEvent(0, evX, 0);
    cudaStreamWaitEvent(0, evB1, 0);
    dim3 g1(NPAIR / 64, FF / 64, NEXP);
    k_efc1<<<g1, 256, SMEM_GEMM>>>(fc1_b, gmult);
    cudaStreamWaitEvent(0, evB2, 0);
    dim3 g2(NPAIR / 64, DDIM / 128, NEXP);
    k_efc2<<<g2, 256, SMEM_GEMM>>>(fc2_b);

    // join + combine
    cudaStreamWaitEvent(0, evC, 0);
    k_comb<<<(TOK * (DDIM / 4) + 255) / 256, 256>>>(out);
}

// round 16
// speedup vs baseline: 1.2360x; 1.0395x over previous
#include <cuda_runtime.h>
#include <cuda_fp16.h>
#include <math.h>
#include <stdint.h>

#define TOK   2048
#define DDIM  1024
#define NEXP  15
#define KTOP  3
#define FF    1024
#define FSH   2048
#define NPAIR (TOK*KTOP)   // 6144

// ---------------- static scratch ----------------
__device__ __align__(16) float g_yp[(size_t)NPAIR * DDIM];        // expert fc2 out
__device__ __align__(16) __half g_xq [(size_t)TOK * DDIM];
__device__ __align__(16) __half g_aq [(size_t)NPAIR * FF];        // expert act (fp16)
__device__ __align__(16) __half g_asq[(size_t)TOK * FSH];         // shared act (fp16)
__device__ __align__(16) __half g_w1q[(size_t)NEXP * 2 * FF * DDIM];
__device__ __align__(16) __half g_w2q[(size_t)NEXP * DDIM * FF];
__device__ __align__(16) __half g_s1q[(size_t)2 * FSH * DDIM];
__device__ __align__(16) __half g_s2q[(size_t)DDIM * FSH];

__device__ int   g_ptok[NPAIR];
__device__ int   g_t2s [TOK * KTOP];
__device__ float g_tw  [TOK * KTOP];
__device__ int   g_ti  [TOK * KTOP];
__device__ int   g_cnt[NEXP], g_off[NEXP];

__device__ __forceinline__ float gelu_exact(float v) {
    return 0.5f * v * (1.0f + erff(v * 0.70710678118654752440f));
}
__device__ __forceinline__ uint32_t smem_u32(const void* p) {
    return (uint32_t)__cvta_generic_to_shared(p);
}
__device__ __forceinline__ uint32_t pack2h(float a, float b) {
    __half2 h = __floats2half2_rn(a, b);
    return *(uint32_t*)&h;
}

// ---------------- conversion kernel: coalesced, 4 float4 per thread ----------------
__global__ void k_cvt(const float4* __restrict__ src, uint2* __restrict__ dst, int n4) {
    int base = blockIdx.x * (blockDim.x * 4) + threadIdx.x;
#pragma unroll
    for (int j = 0; j < 4; j++) {
        int i = base + j * blockDim.x;
        if (i < n4) {
            float4 v = src[i];
            uint2 o;
            o.x = pack2h(v.x, v.y);
            o.y = pack2h(v.z, v.w);
            dst[i] = o;
        }
    }
}

// ---------------- gating ----------------
__global__ void zero_kernel() {
    int i = threadIdx.x;
    if (i < NEXP) g_cnt[i] = 0;
}

__global__ void gate_kernel(const float* __restrict__ x, const float* __restrict__ gw) {
    int t = blockIdx.x;
    int tid = threadIdx.x;   // 128 threads
    float part[NEXP];
#pragma unroll
    for (int e = 0; e < NEXP; e++) part[e] = 0.f;
    const float* xr = x + (size_t)t * DDIM;
    for (int d = tid; d < DDIM; d += 128) {
        float xv = xr[d];
#pragma unroll
        for (int e = 0; e < NEXP; e++) part[e] += xv * gw[e * DDIM + d];
    }
#pragma unroll
    for (int e = 0; e < NEXP; e++)
#pragma unroll
        for (int o = 16; o > 0; o >>= 1)
            part[e] += __shfl_xor_sync(0xFFFFFFFFu, part[e], o);

    __shared__ float red[NEXP][4];
    int w = tid >> 5, l = tid & 31;
    if (l == 0)
#pragma unroll
        for (int e = 0; e < NEXP; e++) red[e][w] = part[e];
    __syncthreads();

    if (tid == 0) {
        float lg[NEXP];
#pragma unroll
        for (int e = 0; e < NEXP; e++)
            lg[e] = red[e][0] + red[e][1] + red[e][2] + red[e][3];
        float mx = lg[0];
#pragma unroll
        for (int e = 1; e < NEXP; e++) mx = fmaxf(mx, lg[e]);
        float s = 0.f, sc[NEXP];
#pragma unroll
        for (int e = 0; e < NEXP; e++) { sc[e] = expf(lg[e] - mx); s += sc[e]; }
        float inv = 1.f / s;
#pragma unroll
        for (int e = 0; e < NEXP; e++) sc[e] *= inv;

        int   idx[KTOP];
        float wv [KTOP];
        float wsum = 0.f;
#pragma unroll
        for (int k = 0; k < KTOP; k++) {
            int   bi = 0;
            float bv = -1.f;
#pragma unroll
            for (int e = 0; e < NEXP; e++)
                if (sc[e] > bv) { bv = sc[e]; bi = e; }
            idx[k] = bi; wv[k] = bv; wsum += bv;
            sc[bi] = -2.f;
        }
        float winv = 1.f / (wsum + 1e-20f);
#pragma unroll
        for (int k = 0; k < KTOP; k++) {
            g_ti[t * KTOP + k] = idx[k];
            g_tw[t * KTOP + k] = wv[k] * winv;
            atomicAdd(&g_cnt[idx[k]], 1);
        }
    }
}

__global__ void route_kernel() {
    __shared__ int cur[NEXP];
    int tid = threadIdx.x;           // 1024
    if (tid == 0) {
        int cum = 0;
        for (int e = 0; e < NEXP; e++) {
            g_off[e] = cum;
            cur[e] = cum;
            cum += g_cnt[e];
        }
    }
    __syncthreads();
#pragma unroll
    for (int rep = 0; rep < 2; rep++) {
        int t = tid + rep * 1024;
        if (t < TOK) {
#pragma unroll
            for (int k = 0; k < KTOP; k++) {
                int e = g_ti[t * KTOP + k];
                int s = atomicAdd(&cur[e], 1);
                g_ptok[s] = t;
                g_t2s[t * KTOP + k] = s;
            }
        }
    }
}

// ---------------- fp16 mma.sync GEMM: CTA 64x128, 8 warps of 32x32, 3-stage cp.async ----------------
#define BK  32
#define TS  80
#define NSTAGE 3
#define TILE_A (64*TS)                 // 5120
#define TILE_BB (128*TS)               // 10240
#define STG_B (TILE_A + TILE_BB)       // 15360
#define SMEM_GEMM (NSTAGE*STG_B)       // 46080

extern __shared__ char smem_dyn[];

__device__ __forceinline__ void cp16(uint32_t dst, const void* src) {
    asm volatile("cp.async.cg.shared.global [%0], [%1], 16;" :: "r"(dst), "l"(src));
}
__device__ __forceinline__ void cp_commit() { asm volatile("cp.async.commit_group;"); }
__device__ __forceinline__ void cp_wait1() { asm volatile("cp.async.wait_group 1;"); }

__device__ __forceinline__ void ldsm4(uint32_t* r, uint32_t addr) {
    asm volatile("ldmatrix.sync.aligned.m8n8.x4.shared.b16 {%0,%1,%2,%3}, [%4];"
                 : "=r"(r[0]), "=r"(r[1]), "=r"(r[2]), "=r"(r[3]) : "r"(addr));
}
__device__ __forceinline__ void mma16816(float* d, const uint32_t* a, const uint32_t* b) {
    asm volatile("mma.sync.aligned.m16n8k16.row.col.f32.f16.f16.f32 "
                 "{%0,%1,%2,%3},{%4,%5,%6,%7},{%8,%9},{%0,%1,%2,%3};"
                 : "+f"(d[0]), "+f"(d[1]), "+f"(d[2]), "+f"(d[3])
                 : "r"(a[0]), "r"(a[1]), "r"(a[2]), "r"(a[3]), "r"(b[0]), "r"(b[1]));
}

template <bool GATHER, bool GEGLU>
__device__ void mm_gemm(const __half* __restrict__ A, int lda,
                        const int* __restrict__ ridx, int M,
                        const __half* __restrict__ B, int ldb,
                        const float* __restrict__ bias,
                        float* __restrict__ C, __half* __restrict__ Cq,
                        int ldc, int K, int H, const float* __restrict__ mult)
{
    int m0 = blockIdx.x * 64;
    if (m0 >= M) return;

    int tid = threadIdx.x;             // 256
    int wid = tid >> 5, lane = tid & 31;
    uint32_t sBase = smem_u32(smem_dyn);

    // ---- A loader: 4 threads per row, one 16B chunk each ----
    int lrowA = tid >> 2, chA = tid & 3;
    int gm = m0 + lrowA;
    int ga = 0;
    if (gm < M) ga = GATHER ? ridx[gm] : gm;
    const __half* pa = A + (size_t)ga * lda + chA * 8;
    uint32_t dstA = (uint32_t)(lrowA * TS + chA * 16);

    // ---- B loader: 2 threads per row, two 16B chunks each ----
    int lrowB = tid >> 1, chB = (tid & 1) * 2;
    int grow;
    if (GEGLU) {
        int b = lrowB >> 3, o = lrowB & 7;
        int f = blockIdx.y * 64 + (b >> 1) * 8 + o;
        grow = (b & 1) ? (H + f) : f;
    } else {
        grow = blockIdx.y * 128 + lrowB;
    }
    const __half* pb = B + (size_t)grow * ldb + chB * 8;
    uint32_t dstB = (uint32_t)(lrowB * TS + chB * 16);

    // ---- warp tile: 2x4 warps of 32x32 ----
    int wm = wid >> 2;
    int wn = wid & 3;
    uint32_t aoff = (uint32_t)((wm * 32 + (lane & 15)) * TS) + ((lane >> 4) << 4);
    uint32_t boff = (uint32_t)((wn * 32 + (lane & 7) + ((lane >> 4) & 1) * 8) * TS)
                  + (((lane >> 3) & 1) << 4);

    float acc[2][4][4];
#pragma unroll
    for (int i = 0; i < 2; i++)
#pragma unroll
        for (int j = 0; j < 4; j++)
#pragma unroll
            for (int c = 0; c < 4; c++) acc[i][j][c] = 0.f;

    int NT = K / BK;

    auto issue = [&](int it) {
        uint32_t sb = sBase + (uint32_t)(it % NSTAGE) * STG_B;
        int k0 = it * BK;
        cp16(sb + dstA, pa + k0);
        cp16(sb + TILE_A + dstB,      pb + k0);
        cp16(sb + TILE_A + dstB + 16, pb + k0 + 8);
    };

    issue(0); cp_commit();
    issue(1); cp_commit();

    for (int it = 0; it < NT; it++) {
        cp_wait1();
        __syncthreads();
        if (it + 2 < NT) { issue(it + 2); }
        cp_commit();

        uint32_t stg = sBase + (uint32_t)(it % NSTAGE) * STG_B;
        uint32_t As = stg + aoff;
        uint32_t Bs = stg + TILE_A + boff;
#pragma unroll
        for (int k16 = 0; k16 < 2; k16++) {
            uint32_t a[2][4], b[2][4];
#pragma unroll
            for (int jj = 0; jj < 2; jj++) ldsm4(b[jj], Bs + jj * 16 * TS + k16 * 32);
#pragma unroll
            for (int i = 0; i < 2; i++) {
                ldsm4(a[i], As + i * 16 * TS + k16 * 32);
#pragma unroll
                for (int j = 0; j < 4; j++)
                    mma16816(acc[i][j], a[i], &b[j >> 1][(j & 1) * 2]);
            }
        }
    }

    int rbase = m0 + wm * 32 + (lane >> 2);

    if (GEGLU) {
#pragma unroll
        for (int jp = 0; jp < 2; jp++) {
            int f = blockIdx.y * 64 + (wn * 2 + jp) * 8 + (lane & 3) * 2;
            float bx0 = bias[f],     bx1 = bias[f + 1];
            float bg0 = bias[H + f], bg1 = bias[H + f + 1];
            float mu0 = mult[f],     mu1 = mult[f + 1];
#pragma unroll
            for (int i = 0; i < 2; i++) {
                int r = rbase + i * 16;
                float* xh = acc[i][2 * jp];
                float* gg = acc[i][2 * jp + 1];
                if (r < M) {
                    float a0 = gelu_exact(gg[0] + bg0) * (xh[0] + bx0) * mu0;
                    float a1 = gelu_exact(gg[1] + bg1) * (xh[1] + bx1) * mu1;
                    *(uint32_t*)(Cq + (size_t)r * H + f) = pack2h(a0, a1);
                }
                if (r + 8 < M) {
                    float a0 = gelu_exact(gg[2] + bg0) * (xh[2] + bx0) * mu0;
                    float a1 = gelu_exact(gg[3] + bg1) * (xh[3] + bx1) * mu1;
                    *(uint32_t*)(Cq + (size_t)(r + 8) * H + f) = pack2h(a0, a1);
                }
            }
        }
    } else {
        int cbase = blockIdx.y * 128 + wn * 32 + (lane & 3) * 2;
#pragma unroll
        for (int i = 0; i < 2; i++) {
#pragma unroll
            for (int j = 0; j < 4; j++) {
                int r = rbase + i * 16;
                int c = cbase + j * 8;
                float b0 = bias[c], b1 = bias[c + 1];
                if (r < M) {
                    float2 o = make_float2(acc[i][j][0] + b0, acc[i][j][1] + b1);
                    *(float2*)(C + (size_t)r * ldc + c) = o;
                }
                if (r + 8 < M) {
                    float2 o = make_float2(acc[i][j][2] + b0, acc[i][j][3] + b1);
                    *(float2*)(C + (size_t)(r + 8) * ldc + c) = o;
                }
            }
        }
    }
}

// ---------------- GEMM wrappers ----------------
__global__ void __launch_bounds__(256, 3) k_efc1(const float* __restrict__ b,
                                                 const float* __restrict__ mult) {
    int e = blockIdx.z;
    int M = g_cnt[e], off = g_off[e];
    mm_gemm<true, true>(g_xq, DDIM, g_ptok + off, M,
                        g_w1q + (size_t)e * 2 * FF * DDIM, DDIM,
                        b + (size_t)e * 2 * FF,
                        nullptr, g_aq + (size_t)off * FF,
                        0, DDIM, FF, mult + (size_t)e * FF);
}

__global__ void __launch_bounds__(256, 3) k_efc2(const float* __restrict__ b) {
    int e = blockIdx.z;
    int M = g_cnt[e], off = g_off[e];
    mm_gemm<false, false>(g_aq + (size_t)off * FF, FF, nullptr, M,
                          g_w2q + (size_t)e * DDIM * FF, FF,
                          b + (size_t)e * DDIM,
                          g_yp + (size_t)off * DDIM, nullptr,
                          DDIM, FF, 0, nullptr);
}

__global__ void __launch_bounds__(256, 3) k_sfc1(const float* __restrict__ b,
                                                 const float* __restrict__ mult) {
    mm_gemm<false, true>(g_xq, DDIM, nullptr, TOK, g_s1q, DDIM, b,
                         nullptr, g_asq, 0, DDIM, FSH, mult);
}

__global__ void __launch_bounds__(256, 3) k_sfc2(const float* __restrict__ b,
                                                 float* __restrict__ out) {
    mm_gemm<false, false>(g_asq, FSH, nullptr, TOK, g_s2q, FSH, b,
                          out, nullptr, DDIM, FSH, 0, nullptr);
}

// ---------------- combine ----------------
__global__ void k_comb(float* __restrict__ out) {
    int i = blockIdx.x * blockDim.x + threadIdx.x;
    const int D4 = DDIM / 4;
    if (i >= TOK * D4) return;
    int t = i / D4, d4 = i % D4;
    float4 acc = *(float4*)(out + (size_t)t * DDIM + d4 * 4);
#pragma unroll
    for (int k = 0; k < KTOP; k++) {
        int s = g_t2s[t * KTOP + k];
        float w = g_tw[t * KTOP + k];
        const float4 v = *(const float4*)(g_yp + (size_t)s * DDIM + d4 * 4);
        acc.x += w * v.x; acc.y += w * v.y; acc.z += w * v.z; acc.w += w * v.w;
    }
    *(float4*)(out + (size_t)t * DDIM + d4 * 4) = acc;
}

// ---------------- launch (round-8 topology) ----------------
extern "C" void kernel_launch(void* const* d_in, const int* in_sizes, int n_in,
                              void* d_out, int out_size) {
    const float* x       = (const float*)d_in[0];
    const float* gate_w  = (const float*)d_in[1];
    const float* fc1_w   = (const float*)d_in[2];
    const float* fc1_b   = (const float*)d_in[3];
    const float* gmult   = (const float*)d_in[4];
    const float* fc2_w   = (const float*)d_in[5];
    const float* fc2_b   = (const float*)d_in[6];
    const float* sfc1_w  = (const float*)d_in[7];
    const float* sfc1_b  = (const float*)d_in[8];
    const float* sgmult  = (const float*)d_in[9];
    const float* sfc2_w  = (const float*)d_in[10];
    const float* sfc2_b  = (const float*)d_in[11];
    float* out = (float*)d_out;

    static bool inited = false;
    static cudaStream_t sB, sC;
    static cudaEvent_t evF, evX, evB1, evB2, evC;
    if (!inited) {
        cudaStreamCreateWithFlags(&sB, cudaStreamNonBlocking);
        cudaStreamCreateWithFlags(&sC, cudaStreamNonBlocking);
        cudaEventCreateWithFlags(&evF,  cudaEventDisableTiming);
        cudaEventCreateWithFlags(&evX,  cudaEventDisableTiming);
        cudaEventCreateWithFlags(&evB1, cudaEventDisableTiming);
        cudaEventCreateWithFlags(&evB2, cudaEventDisableTiming);
        cudaEventCreateWithFlags(&evC,  cudaEventDisableTiming);
        cudaFuncSetAttribute(k_efc1, cudaFuncAttributeMaxDynamicSharedMemorySize, SMEM_GEMM);
        cudaFuncSetAttribute(k_efc2, cudaFuncAttributeMaxDynamicSharedMemorySize, SMEM_GEMM);
        cudaFuncSetAttribute(k_sfc1, cudaFuncAttributeMaxDynamicSharedMemorySize, SMEM_GEMM);
        cudaFuncSetAttribute(k_sfc2, cudaFuncAttributeMaxDynamicSharedMemorySize, SMEM_GEMM);
        inited = true;
    }

    __half *xq, *w1q, *w2q, *s1q, *s2q;
    cudaGetSymbolAddress((void**)&xq,  g_xq);
    cudaGetSymbolAddress((void**)&w1q, g_w1q);
    cudaGetSymbolAddress((void**)&w2q, g_w2q);
    cudaGetSymbolAddress((void**)&s1q, g_s1q);
    cudaGetSymbolAddress((void**)&s2q, g_s2q);

    // fork
    cudaEventRecord(evF, 0);
    cudaStreamWaitEvent(sB, evF, 0);
    cudaStreamWaitEvent(sC, evF, 0);

    // ---- stream L: x conversion + gating + routing ----
    {
        int n4 = TOK * DDIM / 4;
        k_cvt<<<(n4 + 1023) / 1024, 256>>>((const float4*)x, (uint2*)xq, n4);
    }
    cudaEventRecord(evX, 0);
    zero_kernel<<<1, 32>>>();
    gate_kernel<<<TOK, 128>>>(x, gate_w);
    route_kernel<<<1, 1024>>>();

    // ---- stream B: expert weight conversions ----
    {
        int n4 = NEXP * 2 * FF * DDIM / 4;
        k_cvt<<<(n4 + 1023) / 1024, 256, 0, sB>>>((const float4*)fc1_w, (uint2*)w1q, n4);
        cudaEventRecord(evB1, sB);
        n4 = NEXP * DDIM * FF / 4;
        k_cvt<<<(n4 + 1023) / 1024, 256, 0, sB>>>((const float4*)fc2_w, (uint2*)w2q, n4);
        cudaEventRecord(evB2, sB);
    }

    // ---- stream C: shared weight conversions + shared expert chain ----
    {
        int n4 = 2 * FSH * DDIM / 4;
        k_cvt<<<(n4 + 1023) / 1024, 256, 0, sC>>>((const float4*)sfc1_w, (uint2*)s1q, n4);
        n4 = DDIM * FSH / 4;
        k_cvt<<<(n4 + 1023) / 1024, 256, 0, sC>>>((const float4*)sfc2_w, (uint2*)s2q, n4);
        cudaStreamWaitEvent(sC, evX, 0);
        dim3 g3(TOK / 64, FSH / 64);
        k_sfc1<<<g3, 256, SMEM_GEMM, sC>>>(sfc1_b, sgmult);
        dim3 g4(TOK / 64, DDIM / 128);
        k_sfc2<<<g4, 256, SMEM_GEMM, sC>>>(sfc2_b, out);
        cudaEventRecord(evC, sC);
    }

    // ---- stream L: expert chain ----
    cudaStreamWaitEvent(0, evB1, 0);
    dim3 g1(NPAIR / 64, FF / 64, NEXP);
    k_efc1<<<g1, 256, SMEM_GEMM>>>(fc1_b, gmult);
    cudaStreamWaitEvent(0, evB2, 0);
    dim3 g2(NPAIR / 64, DDIM / 128, NEXP);
    k_efc2<<<g2, 256, SMEM_GEMM>>>(fc2_b);

    // join + combine
    cudaStreamWaitEvent(0, evC, 0);
    k_comb<<<(TOK * (DDIM / 4) + 255) / 256, 256>>>(out);
}

// round 17
// speedup vs baseline: 1.2409x; 1.0040x over previous
#include <cuda_runtime.h>
#include <cuda_fp16.h>
#include <math.h>
#include <stdint.h>

#define TOK   2048
#define DDIM  1024
#define NEXP  15
#define KTOP  3
#define FF    1024
#define FSH   2048
#define NPAIR (TOK*KTOP)   // 6144

// ---------------- static scratch ----------------
__device__ __align__(16) __half g_xq [(size_t)TOK * DDIM];
__device__ __align__(16) __half g_aq [(size_t)NPAIR * FF];        // expert act (fp16)
__device__ __align__(16) __half g_asq[(size_t)TOK * FSH];         // shared act (fp16)
__device__ __align__(16) __half g_w1q[(size_t)NEXP * 2 * FF * DDIM];
__device__ __align__(16) __half g_w2q[(size_t)NEXP * DDIM * FF];
__device__ __align__(16) __half g_s1q[(size_t)2 * FSH * DDIM];
__device__ __align__(16) __half g_s2q[(size_t)DDIM * FSH];

__device__ int   g_ptok[NPAIR];
__device__ float g_wsl [NPAIR];           // slot -> gate weight
__device__ float g_tw  [TOK * KTOP];
__device__ int   g_ti  [TOK * KTOP];
__device__ int   g_cnt[NEXP], g_off[NEXP];

__device__ __forceinline__ float gelu_exact(float v) {
    return 0.5f * v * (1.0f + erff(v * 0.70710678118654752440f));
}
__device__ __forceinline__ uint32_t smem_u32(const void* p) {
    return (uint32_t)__cvta_generic_to_shared(p);
}
__device__ __forceinline__ uint32_t pack2h(float a, float b) {
    __half2 h = __floats2half2_rn(a, b);
    return *(uint32_t*)&h;
}

// ---------------- conversion kernel: coalesced, 4 float4 per thread ----------------
__global__ void k_cvt(const float4* __restrict__ src, uint2* __restrict__ dst, int n4) {
    int base = blockIdx.x * (blockDim.x * 4) + threadIdx.x;
#pragma unroll
    for (int j = 0; j < 4; j++) {
        int i = base + j * blockDim.x;
        if (i < n4) {
            float4 v = src[i];
            uint2 o;
            o.x = pack2h(v.x, v.y);
            o.y = pack2h(v.z, v.w);
            dst[i] = o;
        }
    }
}

// ---------------- zero output ----------------
__global__ void k_zero_out(float4* __restrict__ out, int n4) {
    int i = blockIdx.x * blockDim.x + threadIdx.x;
    if (i < n4) out[i] = make_float4(0.f, 0.f, 0.f, 0.f);
}

// ---------------- gating ----------------
__global__ void zero_kernel() {
    int i = threadIdx.x;
    if (i < NEXP) g_cnt[i] = 0;
}

__global__ void gate_kernel(const float* __restrict__ x, const float* __restrict__ gw) {
    int t = blockIdx.x;
    int tid = threadIdx.x;   // 128 threads
    float part[NEXP];
#pragma unroll
    for (int e = 0; e < NEXP; e++) part[e] = 0.f;
    const float* xr = x + (size_t)t * DDIM;
    for (int d = tid; d < DDIM; d += 128) {
        float xv = xr[d];
#pragma unroll
        for (int e = 0; e < NEXP; e++) part[e] += xv * gw[e * DDIM + d];
    }
#pragma unroll
    for (int e = 0; e < NEXP; e++)
#pragma unroll
        for (int o = 16; o > 0; o >>= 1)
            part[e] += __shfl_xor_sync(0xFFFFFFFFu, part[e], o);

    __shared__ float red[NEXP][4];
    int w = tid >> 5, l = tid & 31;
    if (l == 0)
#pragma unroll
        for (int e = 0; e < NEXP; e++) red[e][w] = part[e];
    __syncthreads();

    if (tid == 0) {
        float lg[NEXP];
#pragma unroll
        for (int e = 0; e < NEXP; e++)
            lg[e] = red[e][0] + red[e][1] + red[e][2] + red[e][3];
        float mx = lg[0];
#pragma unroll
        for (int e = 1; e < NEXP; e++) mx = fmaxf(mx, lg[e]);
        float s = 0.f, sc[NEXP];
#pragma unroll
        for (int e = 0; e < NEXP; e++) { sc[e] = expf(lg[e] - mx); s += sc[e]; }
        float inv = 1.f / s;
#pragma unroll
        for (int e = 0; e < NEXP; e++) sc[e] *= inv;

        int   idx[KTOP];
        float wv [KTOP];
        float wsum = 0.f;
#pragma unroll
        for (int k = 0; k < KTOP; k++) {
            int   bi = 0;
            float bv = -1.f;
#pragma unroll
            for (int e = 0; e < NEXP; e++)
                if (sc[e] > bv) { bv = sc[e]; bi = e; }
            idx[k] = bi; wv[k] = bv; wsum += bv;
            sc[bi] = -2.f;
        }
        float winv = 1.f / (wsum + 1e-20f);
#pragma unroll
        for (int k = 0; k < KTOP; k++) {
            g_ti[t * KTOP + k] = idx[k];
            g_tw[t * KTOP + k] = wv[k] * winv;
            atomicAdd(&g_cnt[idx[k]], 1);
        }
    }
}

__global__ void route_kernel() {
    __shared__ int cur[NEXP];
    int tid = threadIdx.x;           // 1024
    if (tid == 0) {
        int cum = 0;
        for (int e = 0; e < NEXP; e++) {
            g_off[e] = cum;
            cur[e] = cum;
            cum += g_cnt[e];
        }
    }
    __syncthreads();
#pragma unroll
    for (int rep = 0; rep < 2; rep++) {
        int t = tid + rep * 1024;
        if (t < TOK) {
#pragma unroll
            for (int k = 0; k < KTOP; k++) {
                int e = g_ti[t * KTOP + k];
                int s = atomicAdd(&cur[e], 1);
                g_ptok[s] = t;
                g_wsl[s] = g_tw[t * KTOP + k];
            }
        }
    }
}

// ---------------- fp16 mma.sync GEMM: CTA 64x128, 8 warps of 32x32, 3-stage cp.async ----------------
#define BK  32
#define TS  80
#define NSTAGE 3
#define TILE_A (64*TS)                 // 5120
#define TILE_BB (128*TS)               // 10240
#define STG_B (TILE_A + TILE_BB)       // 15360
#define SMEM_GEMM (NSTAGE*STG_B)       // 46080

extern __shared__ char smem_dyn[];

__device__ __forceinline__ void cp16(uint32_t dst, const void* src) {
    asm volatile("cp.async.cg.shared.global [%0], [%1], 16;" :: "r"(dst), "l"(src));
}
__device__ __forceinline__ void cp_commit() { asm volatile("cp.async.commit_group;"); }
__device__ __forceinline__ void cp_wait1() { asm volatile("cp.async.wait_group 1;"); }

__device__ __forceinline__ void ldsm4(uint32_t* r, uint32_t addr) {
    asm volatile("ldmatrix.sync.aligned.m8n8.x4.shared.b16 {%0,%1,%2,%3}, [%4];"
                 : "=r"(r[0]), "=r"(r[1]), "=r"(r[2]), "=r"(r[3]) : "r"(addr));
}
__device__ __forceinline__ void mma16816(float* d, const uint32_t* a, const uint32_t* b) {
    asm volatile("mma.sync.aligned.m16n8k16.row.col.f32.f16.f16.f32 "
                 "{%0,%1,%2,%3},{%4,%5,%6,%7},{%8,%9},{%0,%1,%2,%3};"
                 : "+f"(d[0]), "+f"(d[1]), "+f"(d[2]), "+f"(d[3])
                 : "r"(a[0]), "r"(a[1]), "r"(a[2]), "r"(a[3]), "r"(b[0]), "r"(b[1]));
}

// CMODE: 0 = geglu fp16 epilogue; 1 = weighted atomic-add combine (tok/wsl); 2 = plain atomic add
template <bool GATHER, bool GEGLU, int CMODE>
__device__ void mm_gemm(const __half* __restrict__ A, int lda,
                        const int* __restrict__ ridx, int M,
                        const __half* __restrict__ B, int ldb,
                        const float* __restrict__ bias,
                        float* __restrict__ C, __half* __restrict__ Cq,
                        int ldc, int K, int H, const float* __restrict__ mult,
                        const float* __restrict__ wsl)
{
    int m0 = blockIdx.x * 64;
    if (m0 >= M) return;

    int tid = threadIdx.x;             // 256
    int wid = tid >> 5, lane = tid & 31;
    uint32_t sBase = smem_u32(smem_dyn);

    // ---- A loader: 4 threads per row, one 16B chunk each ----
    int lrowA = tid >> 2, chA = tid & 3;
    int gm = m0 + lrowA;
    int ga = 0;
    if (gm < M) ga = GATHER ? ridx[gm] : gm;
    const __half* pa = A + (size_t)ga * lda + chA * 8;
    uint32_t dstA = (uint32_t)(lrowA * TS + chA * 16);

    // ---- B loader: 2 threads per row, two 16B chunks each ----
    int lrowB = tid >> 1, chB = (tid & 1) * 2;
    int grow;
    if (GEGLU) {
        int b = lrowB >> 3, o = lrowB & 7;
        int f = blockIdx.y * 64 + (b >> 1) * 8 + o;
        grow = (b & 1) ? (H + f) : f;
    } else {
        grow = blockIdx.y * 128 + lrowB;
    }
    const __half* pb = B + (size_t)grow * ldb + chB * 8;
    uint32_t dstB = (uint32_t)(lrowB * TS + chB * 16);

    // ---- warp tile: 2x4 warps of 32x32 ----
    int wm = wid >> 2;
    int wn = wid & 3;
    uint32_t aoff = (uint32_t)((wm * 32 + (lane & 15)) * TS) + ((lane >> 4) << 4);
    uint32_t boff = (uint32_t)((wn * 32 + (lane & 7) + ((lane >> 4) & 1) * 8) * TS)
                  + (((lane >> 3) & 1) << 4);

    float acc[2][4][4];
#pragma unroll
    for (int i = 0; i < 2; i++)
#pragma unroll
        for (int j = 0; j < 4; j++)
#pragma unroll
            for (int c = 0; c < 4; c++) acc[i][j][c] = 0.f;

    int NT = K / BK;

    auto issue = [&](int it) {
        uint32_t sb = sBase + (uint32_t)(it % NSTAGE) * STG_B;
        int k0 = it * BK;
        cp16(sb + dstA, pa + k0);
        cp16(sb + TILE_A + dstB,      pb + k0);
        cp16(sb + TILE_A + dstB + 16, pb + k0 + 8);
    };

    issue(0); cp_commit();
    issue(1); cp_commit();

    for (int it = 0; it < NT; it++) {
        cp_wait1();
        __syncthreads();
        if (it + 2 < NT) { issue(it + 2); }
        cp_commit();

        uint32_t stg = sBase + (uint32_t)(it % NSTAGE) * STG_B;
        uint32_t As = stg + aoff;
        uint32_t Bs = stg + TILE_A + boff;
#pragma unroll
        for (int k16 = 0; k16 < 2; k16++) {
            uint32_t a[2][4], b[2][4];
#pragma unroll
            for (int jj = 0; jj < 2; jj++) ldsm4(b[jj], Bs + jj * 16 * TS + k16 * 32);
#pragma unroll
            for (int i = 0; i < 2; i++) {
                ldsm4(a[i], As + i * 16 * TS + k16 * 32);
#pragma unroll
                for (int j = 0; j < 4; j++)
                    mma16816(acc[i][j], a[i], &b[j >> 1][(j & 1) * 2]);
            }
        }
    }

    int rbase = m0 + wm * 32 + (lane >> 2);

    if (GEGLU) {
#pragma unroll
        for (int jp = 0; jp < 2; jp++) {
            int f = blockIdx.y * 64 + (wn * 2 + jp) * 8 + (lane & 3) * 2;
            float bx0 = bias[f],     bx1 = bias[f + 1];
            float bg0 = bias[H + f], bg1 = bias[H + f + 1];
            float mu0 = mult[f],     mu1 = mult[f + 1];
#pragma unroll
            for (int i = 0; i < 2; i++) {
                int r = rbase + i * 16;
                float* xh = acc[i][2 * jp];
                float* gg = acc[i][2 * jp + 1];
                if (r < M) {
                    float a0 = gelu_exact(gg[0] + bg0) * (xh[0] + bx0) * mu0;
                    float a1 = gelu_exact(gg[1] + bg1) * (xh[1] + bx1) * mu1;
                    *(uint32_t*)(Cq + (size_t)r * H + f) = pack2h(a0, a1);
                }
                if (r + 8 < M) {
                    float a0 = gelu_exact(gg[2] + bg0) * (xh[2] + bx0) * mu0;
                    float a1 = gelu_exact(gg[3] + bg1) * (xh[3] + bx1) * mu1;
                    *(uint32_t*)(Cq + (size_t)(r + 8) * H + f) = pack2h(a0, a1);
                }
            }
        }
    } else {
        int cbase = blockIdx.y * 128 + wn * 32 + (lane & 3) * 2;
#pragma unroll
        for (int i = 0; i < 2; i++) {
#pragma unroll
            for (int j = 0; j < 4; j++) {
                int r = rbase + i * 16;
                int c = cbase + j * 8;
                float b0 = bias[c], b1 = bias[c + 1];
                if (r < M) {
                    if (CMODE == 1) {
                        float w = wsl[r];
                        size_t t = (size_t)ridx[r];
                        atomicAdd(C + t * ldc + c,     w * (acc[i][j][0] + b0));
                        atomicAdd(C + t * ldc + c + 1, w * (acc[i][j][1] + b1));
                    } else {
                        atomicAdd(C + (size_t)r * ldc + c,     acc[i][j][0] + b0);
                        atomicAdd(C + (size_t)r * ldc + c + 1, acc[i][j][1] + b1);
                    }
                }
                if (r + 8 < M) {
                    if (CMODE == 1) {
                        float w = wsl[r + 8];
                        size_t t = (size_t)ridx[r + 8];
                        atomicAdd(C + t * ldc + c,     w * (acc[i][j][2] + b0));
                        atomicAdd(C + t * ldc + c + 1, w * (acc[i][j][3] + b1));
                    } else {
                        atomicAdd(C + (size_t)(r + 8) * ldc + c,     acc[i][j][2] + b0);
                        atomicAdd(C + (size_t)(r + 8) * ldc + c + 1, acc[i][j][3] + b1);
                    }
                }
            }
        }
    }
}

// ---------------- GEMM wrappers ----------------
__global__ void __launch_bounds__(256, 3) k_efc1(const float* __restrict__ b,
                                                 const float* __restrict__ mult) {
    int e = blockIdx.z;
    int M = g_cnt[e], off = g_off[e];
    mm_gemm<true, true, 0>(g_xq, DDIM, g_ptok + off, M,
                           g_w1q + (size_t)e * 2 * FF * DDIM, DDIM,
                           b + (size_t)e * 2 * FF,
                           nullptr, g_aq + (size_t)off * FF,
                           0, DDIM, FF, mult + (size_t)e * FF, nullptr);
}

__global__ void __launch_bounds__(256, 3) k_efc2(const float* __restrict__ b,
                                                 float* __restrict__ out) {
    int e = blockIdx.z;
    int M = g_cnt[e], off = g_off[e];
    mm_gemm<false, false, 1>(g_aq + (size_t)off * FF, FF, g_ptok + off, M,
                             g_w2q + (size_t)e * DDIM * FF, FF,
                             b + (size_t)e * DDIM,
                             out, nullptr,
                             DDIM, FF, 0, nullptr, g_wsl + off);
}

__global__ void __launch_bounds__(256, 3) k_sfc1(const float* __restrict__ b,
                                                 const float* __restrict__ mult) {
    mm_gemm<false, true, 0>(g_xq, DDIM, nullptr, TOK, g_s1q, DDIM, b,
                            nullptr, g_asq, 0, DDIM, FSH, mult, nullptr);
}

__global__ void __launch_bounds__(256, 3) k_sfc2(const float* __restrict__ b,
                                                 float* __restrict__ out) {
    mm_gemm<false, false, 2>(g_asq, FSH, nullptr, TOK, g_s2q, FSH, b,
                             out, nullptr, DDIM, FSH, 0, nullptr, nullptr);
}

// ---------------- launch (round-8 topology, fused combine) ----------------
extern "C" void kernel_launch(void* const* d_in, const int* in_sizes, int n_in,
                              void* d_out, int out_size) {
    const float* x       = (const float*)d_in[0];
    const float* gate_w  = (const float*)d_in[1];
    const float* fc1_w   = (const float*)d_in[2];
    const float* fc1_b   = (const float*)d_in[3];
    const float* gmult   = (const float*)d_in[4];
    const float* fc2_w   = (const float*)d_in[5];
    const float* fc2_b   = (const float*)d_in[6];
    const float* sfc1_w  = (const float*)d_in[7];
    const float* sfc1_b  = (const float*)d_in[8];
    const float* sgmult  = (const float*)d_in[9];
    const float* sfc2_w  = (const float*)d_in[10];
    const float* sfc2_b  = (const float*)d_in[11];
    float* out = (float*)d_out;

    static bool inited = false;
    static cudaStream_t sB, sC;
    static cudaEvent_t evF, evX, evB1, evB2, evC;
    if (!inited) {
        cudaStreamCreateWithFlags(&sB, cudaStreamNonBlocking);
        cudaStreamCreateWithFlags(&sC, cudaStreamNonBlocking);
        cudaEventCreateWithFlags(&evF,  cudaEventDisableTiming);
        cudaEventCreateWithFlags(&evX,  cudaEventDisableTiming);
        cudaEventCreateWithFlags(&evB1, cudaEventDisableTiming);
        cudaEventCreateWithFlags(&evB2, cudaEventDisableTiming);
        cudaEventCreateWithFlags(&evC,  cudaEventDisableTiming);
        cudaFuncSetAttribute(k_efc1, cudaFuncAttributeMaxDynamicSharedMemorySize, SMEM_GEMM);
        cudaFuncSetAttribute(k_efc2, cudaFuncAttributeMaxDynamicSharedMemorySize, SMEM_GEMM);
        cudaFuncSetAttribute(k_sfc1, cudaFuncAttributeMaxDynamicSharedMemorySize, SMEM_GEMM);
        cudaFuncSetAttribute(k_sfc2, cudaFuncAttributeMaxDynamicSharedMemorySize, SMEM_GEMM);
        inited = true;
    }

    __half *xq, *w1q, *w2q, *s1q, *s2q;
    cudaGetSymbolAddress((void**)&xq,  g_xq);
    cudaGetSymbolAddress((void**)&w1q, g_w1q);
    cudaGetSymbolAddress((void**)&w2q, g_w2q);
    cudaGetSymbolAddress((void**)&s1q, g_s1q);
    cudaGetSymbolAddress((void**)&s2q, g_s2q);

    // zero output (all epilogues accumulate into it), then fork
    {
        int n4 = TOK * DDIM / 4;
        k_zero_out<<<(n4 + 255) / 256, 256>>>((float4*)out, n4);
    }
    cudaEventRecord(evF, 0);
    cudaStreamWaitEvent(sB, evF, 0);
    cudaStreamWaitEvent(sC, evF, 0);

    // ---- stream L: x conversion + gating + routing ----
    {
        int n4 = TOK * DDIM / 4;
        k_cvt<<<(n4 + 1023) / 1024, 256>>>((const float4*)x, (uint2*)xq, n4);
    }
    cudaEventRecord(evX, 0);
    zero_kernel<<<1, 32>>>();
    gate_kernel<<<TOK, 128>>>(x, gate_w);
    route_kernel<<<1, 1024>>>();

    // ---- stream B: expert weight conversions ----
    {
        int n4 = NEXP * 2 * FF * DDIM / 4;
        k_cvt<<<(n4 + 1023) / 1024, 256, 0, sB>>>((const float4*)fc1_w, (uint2*)w1q, n4);
        cudaEventRecord(evB1, sB);
        n4 = NEXP * DDIM * FF / 4;
        k_cvt<<<(n4 + 1023) / 1024, 256, 0, sB>>>((const float4*)fc2_w, (uint2*)w2q, n4);
        cudaEventRecord(evB2, sB);
    }

    // ---- stream C: shared weight conversions + shared expert chain ----
    {
        int n4 = 2 * FSH * DDIM / 4;
        k_cvt<<<(n4 + 1023) / 1024, 256, 0, sC>>>((const float4*)sfc1_w, (uint2*)s1q, n4);
        n4 = DDIM * FSH / 4;
        k_cvt<<<(n4 + 1023) / 1024, 256, 0, sC>>>((const float4*)sfc2_w, (uint2*)s2q, n4);
        cudaStreamWaitEvent(sC, evX, 0);
        dim3 g3(TOK / 64, FSH / 64);
        k_sfc1<<<g3, 256, SMEM_GEMM, sC>>>(sfc1_b, sgmult);
        dim3 g4(TOK / 64, DDIM / 128);
        k_sfc2<<<g4, 256, SMEM_GEMM, sC>>>(sfc2_b, out);
        cudaEventRecord(evC, sC);
    }

    // ---- stream L: expert chain (efc2 epilogue fuses weighted combine) ----
    cudaStreamWaitEvent(0, evB1, 0);
    dim3 g1(NPAIR / 64, FF / 64, NEXP);
    k_efc1<<<g1, 256, SMEM_GEMM>>>(fc1_b, gmult);
    cudaStreamWaitEvent(0, evB2, 0);
    dim3 g2(NPAIR / 64, DDIM / 128, NEXP);
    k_efc2<<<g2, 256, SMEM_GEMM>>>(fc2_b, out);

    // join shared chain back into the capture stream
    cudaStreamWaitEvent(0, evC, 0);
}